// round 15
// baseline (speedup 1.0000x reference)
#include <cuda_runtime.h>
#include <cstddef>

// PowerSpectrum: out[s,n, l*f^2 + i*f + j] = (2l+1)^{-1/2} * sum_m c_l[s,n,m,i] * c_l[s,n,m,j]
// f = 128, l = 0..3. Output 524 MB -> DRAM-write bound.
//
// CONVERGED CHAMPION: 76.3 us wall (reproduced 5x), 7.1 TB/s effective = ~89%
// of HBM3e spec. Remaining gap is DRAM turnaround/refresh, not kernel-addressable.
// Design pinned by falsifying experiments (R1-R14):
//  - __stcs evict-first stores      (default: +16us; __stwt: +8us)
//  - STG.128 width                  (STG.256/v8: +26us via reg pressure)
//  - __launch_bounds__(256,4), 64 regs (uncapped: 128 regs, occ collapse)
//  - one l-tile per 256-thread block, no per-tile barrier (persistent: +19us)
//  - SMEM-staged tile + LDS.128 broadcasts (pure-GMEM: +2us)
//  - per-l blocks (4l-fused: +3us); raster order / block size neutral
//  - 4-row chunks -> 4 independent acc chains -> 4 contiguous STG.128 per warp iter.

#define NFEAT 128
#define F2    (NFEAT * NFEAT)   // 16384
#define OUT_PER_SN (4 * F2)     // 65536

template <int M>
__device__ __forceinline__ void ps_tile(const float* __restrict__ c,
                                        float* __restrict__ out,
                                        float cg,
                                        float* __restrict__ sc) {
    const int tid = threadIdx.x;

    // Vectorized coalesced tile load: M*128 floats = M*32 float4s
    {
        const float4* __restrict__ c4 = reinterpret_cast<const float4*>(c);
        float4* __restrict__ s4 = reinterpret_cast<float4*>(sc);
        #pragma unroll
        for (int idx = tid; idx < M * (NFEAT / 4); idx += 256)
            s4[idx] = c4[idx];
    }
    __syncthreads();

    const int lane = tid & 31;
    const int w    = tid >> 5;          // warp id 0..7
    const unsigned jq = lane * 4;       // j quad base

    // Per-lane register cache of b[m] = c[m][jq..jq+3]
    float4 b[M];
    #pragma unroll
    for (int m = 0; m < M; m++)
        b[m] = *reinterpret_cast<const float4*>(&sc[m * NFEAT + jq]);

    const int i0 = w * 16;              // warp's 16-row band

    #pragma unroll
    for (int chunk = 0; chunk < 4; chunk++) {
        const int i = i0 + chunk * 4;

        float4 acc0 = make_float4(0.f, 0.f, 0.f, 0.f);
        float4 acc1 = make_float4(0.f, 0.f, 0.f, 0.f);
        float4 acc2 = make_float4(0.f, 0.f, 0.f, 0.f);
        float4 acc3 = make_float4(0.f, 0.f, 0.f, 0.f);

        #pragma unroll
        for (int m = 0; m < M; m++) {
            // One 16B broadcast LDS: a-values for rows i..i+3 of component m
            const float4 a = *reinterpret_cast<const float4*>(&sc[m * NFEAT + i]);
            acc0.x = fmaf(a.x, b[m].x, acc0.x);
            acc0.y = fmaf(a.x, b[m].y, acc0.y);
            acc0.z = fmaf(a.x, b[m].z, acc0.z);
            acc0.w = fmaf(a.x, b[m].w, acc0.w);

            acc1.x = fmaf(a.y, b[m].x, acc1.x);
            acc1.y = fmaf(a.y, b[m].y, acc1.y);
            acc1.z = fmaf(a.y, b[m].z, acc1.z);
            acc1.w = fmaf(a.y, b[m].w, acc1.w);

            acc2.x = fmaf(a.z, b[m].x, acc2.x);
            acc2.y = fmaf(a.z, b[m].y, acc2.y);
            acc2.z = fmaf(a.z, b[m].z, acc2.z);
            acc2.w = fmaf(a.z, b[m].w, acc2.w);

            acc3.x = fmaf(a.w, b[m].x, acc3.x);
            acc3.y = fmaf(a.w, b[m].y, acc3.y);
            acc3.z = fmaf(a.w, b[m].z, acc3.z);
            acc3.w = fmaf(a.w, b[m].w, acc3.w);
        }

        acc0.x *= cg; acc0.y *= cg; acc0.z *= cg; acc0.w *= cg;
        acc1.x *= cg; acc1.y *= cg; acc1.z *= cg; acc1.w *= cg;
        acc2.x *= cg; acc2.y *= cg; acc2.z *= cg; acc2.w *= cg;
        acc3.x *= cg; acc3.y *= cg; acc3.z *= cg; acc3.w *= cg;

        __stcs(reinterpret_cast<float4*>(&out[(size_t)(i + 0) * NFEAT + jq]), acc0);
        __stcs(reinterpret_cast<float4*>(&out[(size_t)(i + 1) * NFEAT + jq]), acc1);
        __stcs(reinterpret_cast<float4*>(&out[(size_t)(i + 2) * NFEAT + jq]), acc2);
        __stcs(reinterpret_cast<float4*>(&out[(size_t)(i + 3) * NFEAT + jq]), acc3);
    }
}

__global__ __launch_bounds__(256, 4)
void PowerSpectrum_86088324481926_kernel(const float* __restrict__ c0,
                                         const float* __restrict__ c1,
                                         const float* __restrict__ c2,
                                         const float* __restrict__ c3,
                                         float* __restrict__ out) {
    __shared__ float sc[7 * NFEAT];   // max tile: 7 x 128

    const size_t sn = blockIdx.x;     // flattened (species, sample)
    const int    l  = blockIdx.y;     // 0..3

    float* o = out + sn * (size_t)OUT_PER_SN + (size_t)l * F2;

    switch (l) {
        case 0: ps_tile<1>(c0 + sn * (size_t)(1 * NFEAT), o, 1.0f,           sc); break;
        case 1: ps_tile<3>(c1 + sn * (size_t)(3 * NFEAT), o, 0.57735026919f, sc); break;
        case 2: ps_tile<5>(c2 + sn * (size_t)(5 * NFEAT), o, 0.44721359550f, sc); break;
        default: ps_tile<7>(c3 + sn * (size_t)(7 * NFEAT), o, 0.37796447301f, sc); break;
    }
}

extern "C" void kernel_launch(void* const* d_in, const int* in_sizes, int n_in,
                              void* d_out, int out_size) {
    const float* c0 = (const float*)d_in[0];
    const float* c1 = (const float*)d_in[1];
    const float* c2 = (const float*)d_in[2];
    const float* c3 = (const float*)d_in[3];
    float* out = (float*)d_out;

    const int SN = in_sizes[0] / NFEAT;   // c_l0 is (S, N, 1, 128)

    dim3 grid(SN, 4);
    PowerSpectrum_86088324481926_kernel<<<grid, 256>>>(c0, c1, c2, c3, out);
}

// round 16
// speedup vs baseline: 1.0050x; 1.0050x over previous
#include <cuda_runtime.h>
#include <cstddef>

// PowerSpectrum: out[s,n, l*f^2 + i*f + j] = (2l+1)^{-1/2} * sum_m c_l[s,n,m,i] * c_l[s,n,m,j]
// f = 128, l = 0..3. Output 524 MB -> DRAM-write bound.
//
// FINAL (converged). 76.3 +/- 1 us wall over 6 reproductions; 7.1 TB/s
// effective = ~89% of HBM3e spec. Binder is the DRAM write path; the residual
// is turnaround/refresh/ECC, not kernel-addressable. Design pinned by 13
// falsifying experiments (R1-R15):
//  - __stcs evict-first stores      (default: +16us; __stwt: +8us)
//  - STG.128 width                  (STG.256/v8: +26us via reg pressure)
//  - __launch_bounds__(256,4), 64 regs (uncapped: 128 regs, occ collapse)
//  - one l-tile per 256-thread block, no per-tile barrier (persistent: +19us)
//  - SMEM-staged tile + LDS.128 broadcasts (pure-GMEM: +2us)
//  - per-l blocks (4l-fused: +3us); raster order / block size neutral
//  - 4-row chunks -> 4 independent acc chains -> 4 contiguous STG.128 per warp iter.

#define NFEAT 128
#define F2    (NFEAT * NFEAT)   // 16384
#define OUT_PER_SN (4 * F2)     // 65536

template <int M>
__device__ __forceinline__ void ps_tile(const float* __restrict__ c,
                                        float* __restrict__ out,
                                        float cg,
                                        float* __restrict__ sc) {
    const int tid = threadIdx.x;

    // Vectorized coalesced tile load: M*128 floats = M*32 float4s
    {
        const float4* __restrict__ c4 = reinterpret_cast<const float4*>(c);
        float4* __restrict__ s4 = reinterpret_cast<float4*>(sc);
        #pragma unroll
        for (int idx = tid; idx < M * (NFEAT / 4); idx += 256)
            s4[idx] = c4[idx];
    }
    __syncthreads();

    const int lane = tid & 31;
    const int w    = tid >> 5;          // warp id 0..7
    const unsigned jq = lane * 4;       // j quad base

    // Per-lane register cache of b[m] = c[m][jq..jq+3]
    float4 b[M];
    #pragma unroll
    for (int m = 0; m < M; m++)
        b[m] = *reinterpret_cast<const float4*>(&sc[m * NFEAT + jq]);

    const int i0 = w * 16;              // warp's 16-row band

    #pragma unroll
    for (int chunk = 0; chunk < 4; chunk++) {
        const int i = i0 + chunk * 4;

        float4 acc0 = make_float4(0.f, 0.f, 0.f, 0.f);
        float4 acc1 = make_float4(0.f, 0.f, 0.f, 0.f);
        float4 acc2 = make_float4(0.f, 0.f, 0.f, 0.f);
        float4 acc3 = make_float4(0.f, 0.f, 0.f, 0.f);

        #pragma unroll
        for (int m = 0; m < M; m++) {
            // One 16B broadcast LDS: a-values for rows i..i+3 of component m
            const float4 a = *reinterpret_cast<const float4*>(&sc[m * NFEAT + i]);
            acc0.x = fmaf(a.x, b[m].x, acc0.x);
            acc0.y = fmaf(a.x, b[m].y, acc0.y);
            acc0.z = fmaf(a.x, b[m].z, acc0.z);
            acc0.w = fmaf(a.x, b[m].w, acc0.w);

            acc1.x = fmaf(a.y, b[m].x, acc1.x);
            acc1.y = fmaf(a.y, b[m].y, acc1.y);
            acc1.z = fmaf(a.y, b[m].z, acc1.z);
            acc1.w = fmaf(a.y, b[m].w, acc1.w);

            acc2.x = fmaf(a.z, b[m].x, acc2.x);
            acc2.y = fmaf(a.z, b[m].y, acc2.y);
            acc2.z = fmaf(a.z, b[m].z, acc2.z);
            acc2.w = fmaf(a.z, b[m].w, acc2.w);

            acc3.x = fmaf(a.w, b[m].x, acc3.x);
            acc3.y = fmaf(a.w, b[m].y, acc3.y);
            acc3.z = fmaf(a.w, b[m].z, acc3.z);
            acc3.w = fmaf(a.w, b[m].w, acc3.w);
        }

        acc0.x *= cg; acc0.y *= cg; acc0.z *= cg; acc0.w *= cg;
        acc1.x *= cg; acc1.y *= cg; acc1.z *= cg; acc1.w *= cg;
        acc2.x *= cg; acc2.y *= cg; acc2.z *= cg; acc2.w *= cg;
        acc3.x *= cg; acc3.y *= cg; acc3.z *= cg; acc3.w *= cg;

        __stcs(reinterpret_cast<float4*>(&out[(size_t)(i + 0) * NFEAT + jq]), acc0);
        __stcs(reinterpret_cast<float4*>(&out[(size_t)(i + 1) * NFEAT + jq]), acc1);
        __stcs(reinterpret_cast<float4*>(&out[(size_t)(i + 2) * NFEAT + jq]), acc2);
        __stcs(reinterpret_cast<float4*>(&out[(size_t)(i + 3) * NFEAT + jq]), acc3);
    }
}

__global__ __launch_bounds__(256, 4)
void PowerSpectrum_86088324481926_kernel(const float* __restrict__ c0,
                                         const float* __restrict__ c1,
                                         const float* __restrict__ c2,
                                         const float* __restrict__ c3,
                                         float* __restrict__ out) {
    __shared__ float sc[7 * NFEAT];   // max tile: 7 x 128

    const size_t sn = blockIdx.x;     // flattened (species, sample)
    const int    l  = blockIdx.y;     // 0..3

    float* o = out + sn * (size_t)OUT_PER_SN + (size_t)l * F2;

    switch (l) {
        case 0: ps_tile<1>(c0 + sn * (size_t)(1 * NFEAT), o, 1.0f,           sc); break;
        case 1: ps_tile<3>(c1 + sn * (size_t)(3 * NFEAT), o, 0.57735026919f, sc); break;
        case 2: ps_tile<5>(c2 + sn * (size_t)(5 * NFEAT), o, 0.44721359550f, sc); break;
        default: ps_tile<7>(c3 + sn * (size_t)(7 * NFEAT), o, 0.37796447301f, sc); break;
    }
}

extern "C" void kernel_launch(void* const* d_in, const int* in_sizes, int n_in,
                              void* d_out, int out_size) {
    const float* c0 = (const float*)d_in[0];
    const float* c1 = (const float*)d_in[1];
    const float* c2 = (const float*)d_in[2];
    const float* c3 = (const float*)d_in[3];
    float* out = (float*)d_out;

    const int SN = in_sizes[0] / NFEAT;   // c_l0 is (S, N, 1, 128)

    dim3 grid(SN, 4);
    PowerSpectrum_86088324481926_kernel<<<grid, 256>>>(c0, c1, c2, c3, out);
}